// round 10
// baseline (speedup 1.0000x reference)
#include <cuda_runtime.h>
#include <cstdint>
#include <math.h>

// BinaryTreeLatentVariable: N_LEAVES=1024, L=16, C=4.
// out[node,o] = parent[node,o] + sL + sR
//             + log( sum_{i,j} expT[o,i,j] * exp(L[i]-sL) * exp(R[j]-sR) )
// (sL, sR any finite shifts — we use a cheap broadcast instead of exact max.)
// Persistent kernel: 256 CTAs x 512 threads (2 CTAs/SM -> 32 warps/SM),
// grid barrier between levels. Warp = (output g of CTA's 4, i-quarter q).

#define OC 64
#define OG 16          // o-groups; each CTA owns 4 outputs
#define XS 16          // node slices
#define NCTA (OG * XS) // 256
#define ELS 20         // eLs row stride (floats): 16B-aligned, 4-way STS conflicts

__device__ float g_ET[OC * 4096];    // 1 MB: exp(trans) repacked [o][i][j]
__device__ float g_bufA[512 * OC];
__device__ float g_bufB[512 * OC];
__device__ unsigned int g_bar;

// ---- packed f32x2 helpers (FFMA2) ------------------------------------------
__device__ __forceinline__ unsigned long long pack2(float x, float y) {
    unsigned long long r;
    asm("mov.b64 %0, {%1, %2};" : "=l"(r) : "f"(x), "f"(y));
    return r;
}
__device__ __forceinline__ void unpack2(unsigned long long v, float& x, float& y) {
    asm("mov.b64 {%0, %1}, %2;" : "=f"(x), "=f"(y) : "l"(v));
}
__device__ __forceinline__ void ffma2(unsigned long long& d,
                                      unsigned long long a, unsigned long long b) {
    asm("fma.rn.f32x2 %0, %1, %2, %0;" : "+l"(d) : "l"(a), "l"(b));
}

// ---- butterfly multi-value warp allreduce ----------------------------------
// NV independent 32-lane sums in ~NV SHFL total. On return each lane holds
// the full sum of value idx(lane).
template <int NV>
__device__ __forceinline__ float butterflyN(float s[NV], int lane) {
    #pragma unroll
    for (int k = 0; k < 5; k++) {
        const int w = 16 >> k;
        const int m = (NV / 2) >> k;
        if (m >= 1) {
            const bool up = (lane & w) != 0;
            #pragma unroll
            for (int i = 0; i < m; i++) {
                float t = up ? s[i] : s[i + m];
                float r = __shfl_xor_sync(0xffffffffu, t, w);
                s[i] = (up ? s[i + m] : s[i]) + r;
            }
        } else {
            s[0] += __shfl_xor_sync(0xffffffffu, s[0], w);
        }
    }
    return s[0];
}
template <int NV>
__device__ __forceinline__ int butterfly_idx(int lane) {
    int idx = 0;
    #pragma unroll
    for (int k = 0; k < 5; k++) {
        const int m = (NV / 2) >> k;
        if (m >= 1) idx += ((lane >> (4 - k)) & 1) * m;
    }
    return idx;
}

// ---- Prologue: ET[o][i][j] = exp(trans[...]); reset grid barrier -----------
__global__ void expT_kernel(const float* __restrict__ trans) {
    if (blockIdx.x == 0 && threadIdx.x == 0) g_bar = 0u;
    int idx = blockIdx.x * 256 + threadIdx.x;   // 0 .. 262143
    int o = idx >> 12, i = (idx >> 6) & 63, j = idx & 63;
    int lp = o >> 2, cp = o & 3;
    int ll = i >> 2, cl = i & 3;
    int lr = j >> 2, cr = j & 3;
    int src = ((((lp * 16 + ll) * 16 + lr) * 4 + cp) * 4 + cl) * 4 + cr;
    g_ET[idx] = expf(trans[src]);
}

// ---- prefetch one chunk: warp w loads node nodeBase+w; parents per-thread --
template <int NBX>
__device__ __forceinline__ void prefetch_chunk(
    float* P, float& pPar, int nodeBase, int nend,
    const float* __restrict__ child, const float* __restrict__ parent,
    int og, int tid, int warp, int lane)
{
    const int node = nodeBase + warp;
    if (warp < NBX && node < nend) {
        const float* L = child + (size_t)(2 * node) * OC;
        P[0] = L[lane];       P[1] = L[lane + 32];
        P[2] = L[lane + 64];  P[3] = L[lane + 96];
    }
    if (tid < 4 * NBX) {
        const int nb = tid & (NBX - 1);
        const int node2 = nodeBase + nb;
        if (node2 < nend)
            pPar = parent[(size_t)node2 * OC + og * 4 + tid / NBX];
    }
}

// ---------------------------------------------------------------------------
// One chunk of NBX nodes. 16 warps: warp w -> output g=w>>2 of the CTA's four,
// i-quarter q=w&3 (16 i's). Lane owns j = {2*lane, 2*lane+1}.
// ---------------------------------------------------------------------------
template <int NBX>
__device__ __forceinline__ void do_chunk(
    int nodeBase, int nend, bool last,
    const float* __restrict__ child, const float* __restrict__ parent,
    float* __restrict__ out,
    const float* ET_s, float* eLs, float* eRs, float* base_s, float* part,
    float* P, float& pPar, int cb, int og, int tid, int warp, int lane,
    int g, int q)
{
    constexpr int NP = NBX / 2;
    const float pcur = pPar;

    float* eLb   = eLs    + cb * (64 * ELS);
    float* eRb   = eRs    + cb * 1024;
    float* baseb = base_s + cb * 16;
    float* partb = part   + cb * 256;

    // ---- consume prefetched children: cheap shift -> exp -> smem ----
    if (warp < NBX) {
        const int node = nodeBase + warp;
        if (node < nend) {
            // Stabilizer: broadcast of lane 0's pairwise max (exact lse shift;
            // within-node spread is a few units, so no overflow risk).
            float sL = __shfl_sync(0xffffffffu, fmaxf(P[0], P[1]), 0);
            float sR = __shfl_sync(0xffffffffu, fmaxf(P[2], P[3]), 0);
            eLb[lane * ELS + warp]        = __expf(P[0] - sL);
            eLb[(lane + 32) * ELS + warp] = __expf(P[1] - sL);
            eRb[warp * 64 + lane]         = __expf(P[2] - sR);
            eRb[warp * 64 + lane + 32]    = __expf(P[3] - sR);
            if (lane == 0) baseb[warp] = sL + sR;
        } else {
            eLb[lane * ELS + warp] = 0.0f;  eLb[(lane + 32) * ELS + warp] = 0.0f;
            eRb[warp * 64 + lane]  = 0.0f;  eRb[warp * 64 + lane + 32]    = 0.0f;
            if (lane == 0) baseb[warp] = 0.0f;
        }
    }
    __syncthreads();

    // ---- prefetch next chunk (LDG latency hidden under mainloop) ----
    if (!last)
        prefetch_chunk<NBX>(P, pPar, nodeBase + NBX, nend, child, parent,
                            og, tid, warp, lane);

    // ---- mainloop: 16 i's, FFMA2 over NBX accumulator pairs ----
    unsigned long long A0[NP], A1[NP];
    #pragma unroll
    for (int p = 0; p < NP; p++) { A0[p] = 0ull; A1[p] = 0ull; }

    const float2* ets = reinterpret_cast<const float2*>(ET_s + (size_t)g * 4096);
    const int ib = q * 16;
    #pragma unroll
    for (int ii = 0; ii < 16; ii++) {
        const int i = ib + ii;
        float2 e = ets[i * 32 + lane];               // ET[o, i, 2lane..+1]
        unsigned long long exx = pack2(e.x, e.x);
        unsigned long long eyy = pack2(e.y, e.y);
        const ulonglong2* el2 = reinterpret_cast<const ulonglong2*>(eLb + i * ELS);
        #pragma unroll
        for (int pp = 0; pp < NBX / 4; pp++) {
            ulonglong2 w = el2[pp];                  // 4 nodes, one LDS.128
            ffma2(A0[2 * pp],     exx, w.x);
            ffma2(A1[2 * pp],     eyy, w.x);
            ffma2(A0[2 * pp + 1], exx, w.y);
            ffma2(A1[2 * pp + 1], eyy, w.y);
        }
    }

    // ---- fold eR, butterfly-reduce NBX sums, one predicated STS ----
    float s[NBX];
    #pragma unroll
    for (int p = 0; p < NP; p++) {
        float a0x, a0y, a1x, a1y;
        unpack2(A0[p], a0x, a0y);
        unpack2(A1[p], a1x, a1y);
        float2 er0 = reinterpret_cast<const float2*>(eRb + (2 * p) * 64)[lane];
        float2 er1 = reinterpret_cast<const float2*>(eRb + (2 * p + 1) * 64)[lane];
        s[2 * p]     = a0x * er0.x + a1x * er0.y;
        s[2 * p + 1] = a0y * er1.x + a1y * er1.y;
    }
    float v = butterflyN<NBX>(s, lane);
    const int idx = butterfly_idx<NBX>(lane);
    if ((lane & (32 / NBX - 1)) == 0)
        partb[(g * 16 + idx) * 4 + q] = v;
    __syncthreads();

    // ---- epilogue: combine quarters, log, write (parent prefetched) ----
    if (tid < 4 * NBX) {
        const int gg = tid / NBX, nb = tid & (NBX - 1);
        const int node = nodeBase + nb;
        if (node < nend) {
            const float* pr = partb + (gg * 16 + nb) * 4;
            float vv = (pr[0] + pr[1]) + (pr[2] + pr[3]);
            out[(size_t)node * OC + og * 4 + gg] = pcur + baseb[nb] + __logf(vv);
        }
    }
}

// ---------------------------------------------------------------------------
// Persistent tree kernel: all 10 levels, grid barrier between them.
// ---------------------------------------------------------------------------
__global__ __launch_bounds__(512, 2) void tree_kernel(
    const float* __restrict__ node_state, float* __restrict__ d_out)
{
    extern __shared__ float smem[];
    float* ET_s   = smem;                  // 4 o * 4096 = 16384 floats (64 KB)
    float* eLs    = smem + 16384;          // 2 x [64][ELS]
    float* eRs    = eLs + 2 * 64 * ELS;    // 2 x [16][64]
    float* base_s = eRs + 2048;            // 2 x 16
    float* part   = base_s + 32;           // 2 x [g][nb][q] = 2 x 256

    const int tid  = threadIdx.x;
    const int warp = tid >> 5;
    const int lane = tid & 31;
    const int og   = blockIdx.x & (OG - 1);
    const int xs   = blockIdx.x >> 4;      // 0..15
    const int g    = warp >> 2;            // output within CTA's four
    const int q    = warp & 3;             // i-quarter

    // ---- one-time ET slice fill: 64 KB via cp.async ----
    {
        unsigned int dst;
        asm("{ .reg .u64 t; cvta.to.shared.u64 t, %1; cvt.u32.u64 %0, t; }"
            : "=r"(dst) : "l"(ET_s));
        const float4* src = reinterpret_cast<const float4*>(g_ET)
                            + (size_t)og * 4096;
        #pragma unroll
        for (int t = 0; t < 8; t++) {
            int e = tid + t * 512;
            asm volatile("cp.async.cg.shared.global [%0], [%1], 16;"
                         :: "r"(dst + 16u * (unsigned)e), "l"(src + e));
        }
        asm volatile("cp.async.commit_group;");
        asm volatile("cp.async.wait_group 0;");
    }
    __syncthreads();

    const float* leaves = node_state + (size_t)1023 * OC;
    float P[4];
    float pPar = 0.0f;

    #pragma unroll 1
    for (int l = 0; l < 10; l++) {
        const int n = 512 >> l;
        const float* child = (l == 0) ? leaves : ((l & 1) ? g_bufA : g_bufB);
        float* out = (l == 9) ? d_out : ((l & 1) ? g_bufB : g_bufA);
        const float* parent = node_state + (size_t)(n - 1) * OC;

        const int npc    = (n + XS - 1) / XS;
        const int nstart = xs * npc;
        const int nend   = (nstart + npc < n) ? (nstart + npc) : n;

        if (nstart < n) {
            if (npc >= 16) {
                prefetch_chunk<16>(P, pPar, nstart, nend, child, parent,
                                   og, tid, warp, lane);
                int cb = 0;
                for (int nb0 = nstart; nb0 < nend; nb0 += 16, cb ^= 1)
                    do_chunk<16>(nb0, nend, nb0 + 16 >= nend, child, parent, out,
                                 ET_s, eLs, eRs, base_s, part,
                                 P, pPar, cb, og, tid, warp, lane, g, q);
            } else if (npc == 8) {
                prefetch_chunk<8>(P, pPar, nstart, nend, child, parent,
                                  og, tid, warp, lane);
                do_chunk<8>(nstart, nend, true, child, parent, out,
                            ET_s, eLs, eRs, base_s, part,
                            P, pPar, 0, og, tid, warp, lane, g, q);
            } else {
                prefetch_chunk<4>(P, pPar, nstart, nend, child, parent,
                                  og, tid, warp, lane);
                int cb = 0;
                for (int nb0 = nstart; nb0 < nend; nb0 += 4, cb ^= 1)
                    do_chunk<4>(nb0, nend, nb0 + 4 >= nend, child, parent, out,
                                ET_s, eLs, eRs, base_s, part,
                                P, pPar, cb, og, tid, warp, lane, g, q);
            }
        }

        // ---- grid barrier (release/acquire, except after last level) ----
        if (l < 9) {
            __syncthreads();
            if (tid == 0) {
                asm volatile("red.release.gpu.global.add.u32 [%0], 1;"
                             :: "l"(&g_bar) : "memory");
                const unsigned int tgt = (unsigned int)(l + 1) * NCTA;
                unsigned int cur;
                do {
                    asm volatile("ld.acquire.gpu.global.u32 %0, [%1];"
                                 : "=r"(cur) : "l"(&g_bar) : "memory");
                } while (cur < tgt);
            }
            __syncthreads();
        }
    }
}

// ---------------------------------------------------------------------------
// Host side
// ---------------------------------------------------------------------------
#define TREE_SMEM ((16384 + 2 * 64 * ELS + 2048 + 32 + 512) * 4)

extern "C" void kernel_launch(void* const* d_in, const int* in_sizes, int n_in,
                              void* d_out, int out_size)
{
    const float* node_state = (const float*)d_in[0];
    const float* trans      = (const float*)d_in[1];
    if (n_in >= 2 && in_sizes[0] == 262144) {   // defensive input identification
        const float* t = node_state; node_state = trans; trans = t;
    }

    cudaFuncSetAttribute(tree_kernel,
                         cudaFuncAttributeMaxDynamicSharedMemorySize, TREE_SMEM);

    expT_kernel<<<1024, 256>>>(trans);
    tree_kernel<<<NCTA, 512, TREE_SMEM>>>(node_state, (float*)d_out);
}

// round 12
// speedup vs baseline: 1.0856x; 1.0856x over previous
#include <cuda_runtime.h>
#include <cstdint>
#include <math.h>

// BinaryTreeLatentVariable: N_LEAVES=1024, L=16, C=4.
// out[node,o] = parent[node,o] + sL + sR
//             + log( sum_{i,j} expT[o,i,j] * exp(L[i]-sL) * exp(R[j]-sR) )
// Persistent kernel: 256 CTAs x 512 threads. R11: slice-local dataflow sync
// (per-(level,slice) counters, 16 producers each) instead of a global grid
// barrier; per-level distinct buffers (no WAR); idle-CTA early exit.

#define OC 64
#define OG 16          // o-groups; each CTA owns 4 outputs
#define XS 16          // node slices
#define NCTA (OG * XS) // 256
#define ELS 20         // eLs row stride (floats): 16B-aligned, 4-way STS conflicts

__device__ float g_ET[OC * 4096];      // 1 MB: exp(trans) repacked [o][i][j]
__device__ float g_buf[1023 * OC];     // per-level output buffers, no reuse
__device__ unsigned int g_cnt[160];    // [level][slice] arrival counters

// ---- packed f32x2 helpers (FFMA2) ------------------------------------------
__device__ __forceinline__ unsigned long long pack2(float x, float y) {
    unsigned long long r;
    asm("mov.b64 %0, {%1, %2};" : "=l"(r) : "f"(x), "f"(y));
    return r;
}
__device__ __forceinline__ void unpack2(unsigned long long v, float& x, float& y) {
    asm("mov.b64 {%0, %1}, %2;" : "=f"(x), "=f"(y) : "l"(v));
}
__device__ __forceinline__ void ffma2(unsigned long long& d,
                                      unsigned long long a, unsigned long long b) {
    asm("fma.rn.f32x2 %0, %1, %2, %0;" : "+l"(d) : "l"(a), "l"(b));
}

// ---- butterfly multi-value warp allreduce ----------------------------------
template <int NV>
__device__ __forceinline__ float butterflyN(float s[NV], int lane) {
    #pragma unroll
    for (int k = 0; k < 5; k++) {
        const int w = 16 >> k;
        const int m = (NV / 2) >> k;
        if (m >= 1) {
            const bool up = (lane & w) != 0;
            #pragma unroll
            for (int i = 0; i < m; i++) {
                float t = up ? s[i] : s[i + m];
                float r = __shfl_xor_sync(0xffffffffu, t, w);
                s[i] = (up ? s[i + m] : s[i]) + r;
            }
        } else {
            s[0] += __shfl_xor_sync(0xffffffffu, s[0], w);
        }
    }
    return s[0];
}
template <int NV>
__device__ __forceinline__ int butterfly_idx(int lane) {
    int idx = 0;
    #pragma unroll
    for (int k = 0; k < 5; k++) {
        const int m = (NV / 2) >> k;
        if (m >= 1) idx += ((lane >> (4 - k)) & 1) * m;
    }
    return idx;
}

// ---- Prologue: ET[o][i][j] = exp(trans[...]); reset all counters -----------
__global__ void expT_kernel(const float* __restrict__ trans) {
    if (blockIdx.x == 0 && threadIdx.x < 160) g_cnt[threadIdx.x] = 0u;
    int idx = blockIdx.x * 256 + threadIdx.x;   // 0 .. 262143
    int o = idx >> 12, i = (idx >> 6) & 63, j = idx & 63;
    int lp = o >> 2, cp = o & 3;
    int ll = i >> 2, cl = i & 3;
    int lr = j >> 2, cr = j & 3;
    int src = ((((lp * 16 + ll) * 16 + lr) * 4 + cp) * 4 + cl) * 4 + cr;
    g_ET[idx] = expf(trans[src]);
}

// ---- prefetch helpers ------------------------------------------------------
template <int NBX>
__device__ __forceinline__ void prefetch_children(
    float* P, int nodeBase, int nend,
    const float* __restrict__ child, int warp, int lane)
{
    const int node = nodeBase + warp;
    if (warp < NBX && node < nend) {
        const float* L = child + (size_t)(2 * node) * OC;
        P[0] = L[lane];       P[1] = L[lane + 32];
        P[2] = L[lane + 64];  P[3] = L[lane + 96];
    }
}
template <int NBX>
__device__ __forceinline__ void prefetch_parent(
    float& pPar, int nodeBase, int nend,
    const float* __restrict__ parent, int og, int tid)
{
    if (tid < 4 * NBX) {
        const int nb = tid & (NBX - 1);
        const int node = nodeBase + nb;
        if (node < nend)
            pPar = parent[(size_t)node * OC + og * 4 + tid / NBX];
    }
}

// ---------------------------------------------------------------------------
// One chunk of NBX nodes. 16 warps: warp w -> output g=w>>2 of the CTA's four,
// i-quarter q=w&3 (16 i's). Lane owns j = {2*lane, 2*lane+1}.
// ---------------------------------------------------------------------------
template <int NBX>
__device__ __forceinline__ void do_chunk(
    int nodeBase, int nend, bool last,
    const float* __restrict__ child, const float* __restrict__ parent,
    float* __restrict__ out,
    const float* ET_s, float* eLs, float* eRs, float* base_s, float* part,
    float* P, float& pPar, int cb, int og, int tid, int warp, int lane,
    int g, int q)
{
    constexpr int NP = NBX / 2;
    const float pcur = pPar;

    float* eLb   = eLs    + cb * (64 * ELS);
    float* eRb   = eRs    + cb * 1024;
    float* baseb = base_s + cb * 16;
    float* partb = part   + cb * 256;

    // ---- consume prefetched children: cheap shift -> exp -> smem ----
    if (warp < NBX) {
        const int node = nodeBase + warp;
        if (node < nend) {
            float sL = __shfl_sync(0xffffffffu, fmaxf(P[0], P[1]), 0);
            float sR = __shfl_sync(0xffffffffu, fmaxf(P[2], P[3]), 0);
            eLb[lane * ELS + warp]        = __expf(P[0] - sL);
            eLb[(lane + 32) * ELS + warp] = __expf(P[1] - sL);
            eRb[warp * 64 + lane]         = __expf(P[2] - sR);
            eRb[warp * 64 + lane + 32]    = __expf(P[3] - sR);
            if (lane == 0) baseb[warp] = sL + sR;
        } else {
            eLb[lane * ELS + warp] = 0.0f;  eLb[(lane + 32) * ELS + warp] = 0.0f;
            eRb[warp * 64 + lane]  = 0.0f;  eRb[warp * 64 + lane + 32]    = 0.0f;
            if (lane == 0) baseb[warp] = 0.0f;
        }
    }
    __syncthreads();

    // ---- prefetch next chunk (latency hidden under mainloop) ----
    if (!last) {
        prefetch_children<NBX>(P, nodeBase + NBX, nend, child, warp, lane);
        prefetch_parent<NBX>(pPar, nodeBase + NBX, nend, parent, og, tid);
    }

    // ---- mainloop: 16 i's, FFMA2 over NBX accumulator pairs ----
    unsigned long long A0[NP], A1[NP];
    #pragma unroll
    for (int p = 0; p < NP; p++) { A0[p] = 0ull; A1[p] = 0ull; }

    const float2* ets = reinterpret_cast<const float2*>(ET_s + (size_t)g * 4096);
    const int ib = q * 16;
    #pragma unroll
    for (int ii = 0; ii < 16; ii++) {
        const int i = ib + ii;
        float2 e = ets[i * 32 + lane];               // ET[o, i, 2lane..+1]
        unsigned long long exx = pack2(e.x, e.x);
        unsigned long long eyy = pack2(e.y, e.y);
        const ulonglong2* el2 = reinterpret_cast<const ulonglong2*>(eLb + i * ELS);
        #pragma unroll
        for (int pp = 0; pp < NBX / 4; pp++) {
            ulonglong2 w = el2[pp];                  // 4 nodes, one LDS.128
            ffma2(A0[2 * pp],     exx, w.x);
            ffma2(A1[2 * pp],     eyy, w.x);
            ffma2(A0[2 * pp + 1], exx, w.y);
            ffma2(A1[2 * pp + 1], eyy, w.y);
        }
    }

    // ---- fold eR, butterfly-reduce NBX sums, one predicated STS ----
    float s[NBX];
    #pragma unroll
    for (int p = 0; p < NP; p++) {
        float a0x, a0y, a1x, a1y;
        unpack2(A0[p], a0x, a0y);
        unpack2(A1[p], a1x, a1y);
        float2 er0 = reinterpret_cast<const float2*>(eRb + (2 * p) * 64)[lane];
        float2 er1 = reinterpret_cast<const float2*>(eRb + (2 * p + 1) * 64)[lane];
        s[2 * p]     = a0x * er0.x + a1x * er0.y;
        s[2 * p + 1] = a0y * er1.x + a1y * er1.y;
    }
    float v = butterflyN<NBX>(s, lane);
    const int idx = butterfly_idx<NBX>(lane);
    if ((lane & (32 / NBX - 1)) == 0)
        partb[(g * 16 + idx) * 4 + q] = v;
    __syncthreads();

    // ---- epilogue: combine quarters, log, write (parent prefetched) ----
    if (tid < 4 * NBX) {
        const int gg = tid / NBX, nb = tid & (NBX - 1);
        const int node = nodeBase + nb;
        if (node < nend) {
            const float* pr = partb + (gg * 16 + nb) * 4;
            float vv = (pr[0] + pr[1]) + (pr[2] + pr[3]);
            out[(size_t)node * OC + og * 4 + gg] = pcur + baseb[nb] + __logf(vv);
        }
    }
}

// ---- counter wait (tid0) ---------------------------------------------------
__device__ __forceinline__ void wait_cnt(const unsigned int* c) {
    unsigned int cur;
    do {
        asm volatile("ld.acquire.gpu.global.u32 %0, [%1];"
                     : "=r"(cur) : "l"(c) : "memory");
    } while (cur < 16u);
}

// ---------------------------------------------------------------------------
// Persistent tree kernel: slice-local dataflow across the 10 levels.
// ---------------------------------------------------------------------------
__global__ __launch_bounds__(512, 2) void tree_kernel(
    const float* __restrict__ node_state, float* __restrict__ d_out)
{
    extern __shared__ float smem[];
    float* ET_s   = smem;                  // 4 o * 4096 = 16384 floats (64 KB)
    float* eLs    = smem + 16384;          // 2 x [64][ELS]
    float* eRs    = eLs + 2 * 64 * ELS;    // 2 x [16][64]
    float* base_s = eRs + 2048;            // 2 x 16
    float* part   = base_s + 32;           // 2 x 256

    const int tid  = threadIdx.x;
    const int warp = tid >> 5;
    const int lane = tid & 31;
    const int og   = blockIdx.x & (OG - 1);
    const int xs   = blockIdx.x >> 4;      // 0..15
    const int g    = warp >> 2;            // output within CTA's four
    const int q    = warp & 3;             // i-quarter

    // ---- one-time ET slice fill: 64 KB via cp.async ----
    {
        unsigned int dst;
        asm("{ .reg .u64 t; cvta.to.shared.u64 t, %1; cvt.u32.u64 %0, t; }"
            : "=r"(dst) : "l"(ET_s));
        const float4* src = reinterpret_cast<const float4*>(g_ET)
                            + (size_t)og * 4096;
        #pragma unroll
        for (int t = 0; t < 8; t++) {
            int e = tid + t * 512;
            asm volatile("cp.async.cg.shared.global [%0], [%1], 16;"
                         :: "r"(dst + 16u * (unsigned)e), "l"(src + e));
        }
        asm volatile("cp.async.commit_group;");
        asm volatile("cp.async.wait_group 0;");
    }
    __syncthreads();

    const float* leaves = node_state + (size_t)1023 * OC;
    float P[4];
    float pPar = 0.0f;

    #pragma unroll 1
    for (int l = 0; l < 10; l++) {
        const int n   = 512 >> l;
        const int npc = (n + XS - 1) / XS;
        const int nstart = xs * npc;
        if (nstart >= n) return;           // idle forever: nobody waits on us
        const int nend = (nstart + npc < n) ? (nstart + npc) : n;

        // per-level distinct buffers: out of level k lives at nodes
        // [1024 - (1024>>k), ...). Level 9 writes d_out.
        const float* child = (l == 0) ? leaves
                           : g_buf + (size_t)(1024 - (2048 >> l)) * OC;
        float* out = (l == 9) ? d_out
                   : g_buf + (size_t)(1024 - (1024 >> l)) * OC;
        const float* parent = node_state + (size_t)(n - 1) * OC;

        const int NBX0 = (npc >= 16) ? 16 : (npc == 8 ? 8 : 4);

        // ---- parent prefetch (pure input) overlaps the wait ----
        if (NBX0 == 16)      prefetch_parent<16>(pPar, nstart, nend, parent, og, tid);
        else if (NBX0 == 8)  prefetch_parent<8 >(pPar, nstart, nend, parent, og, tid);
        else                 prefetch_parent<4 >(pPar, nstart, nend, parent, og, tid);

        // ---- dataflow wait: only this slice's producers ----
        if (l > 0) {
            if (tid == 0) {
                if (n >= 16) {
                    wait_cnt(&g_cnt[(l - 1) * 16 + xs]);
                } else {
                    wait_cnt(&g_cnt[(l - 1) * 16 + 2 * xs]);
                    wait_cnt(&g_cnt[(l - 1) * 16 + 2 * xs + 1]);
                }
            }
            __syncthreads();
        }

        // ---- chunks ----
        if (NBX0 == 16) {
            prefetch_children<16>(P, nstart, nend, child, warp, lane);
            int cb = 0;
            for (int nb0 = nstart; nb0 < nend; nb0 += 16, cb ^= 1)
                do_chunk<16>(nb0, nend, nb0 + 16 >= nend, child, parent, out,
                             ET_s, eLs, eRs, base_s, part,
                             P, pPar, cb, og, tid, warp, lane, g, q);
        } else if (NBX0 == 8) {
            prefetch_children<8>(P, nstart, nend, child, warp, lane);
            do_chunk<8>(nstart, nend, true, child, parent, out,
                        ET_s, eLs, eRs, base_s, part,
                        P, pPar, 0, og, tid, warp, lane, g, q);
        } else {
            prefetch_children<4>(P, nstart, nend, child, warp, lane);
            do_chunk<4>(nstart, nend, true, child, parent, out,
                        ET_s, eLs, eRs, base_s, part,
                        P, pPar, 0, og, tid, warp, lane, g, q);
        }

        // ---- arrival: all threads' STGs done -> release one count ----
        __syncthreads();
        if (tid == 0 && l < 9) {
            asm volatile("red.release.gpu.global.add.u32 [%0], 1;"
                         :: "l"(&g_cnt[l * 16 + xs]) : "memory");
        }
    }
}

// ---------------------------------------------------------------------------
// Host side
// ---------------------------------------------------------------------------
#define TREE_SMEM ((16384 + 2 * 64 * ELS + 2048 + 32 + 512) * 4)

extern "C" void kernel_launch(void* const* d_in, const int* in_sizes, int n_in,
                              void* d_out, int out_size)
{
    const float* node_state = (const float*)d_in[0];
    const float* trans      = (const float*)d_in[1];
    if (n_in >= 2 && in_sizes[0] == 262144) {   // defensive input identification
        const float* t = node_state; node_state = trans; trans = t;
    }

    cudaFuncSetAttribute(tree_kernel,
                         cudaFuncAttributeMaxDynamicSharedMemorySize, TREE_SMEM);

    expT_kernel<<<1024, 256>>>(trans);
    tree_kernel<<<NCTA, 512, TREE_SMEM>>>(node_state, (float*)d_out);
}